// round 6
// baseline (speedup 1.0000x reference)
#include <cuda_runtime.h>

#define BB 32
#define NN 4096
#define DD 256
#define HH 8
#define TT 28
#define ROWS (BB * NN)
#define BLK 128
#define RPB 32              // rows per block (4 threads per row)

typedef unsigned long long u64;

// ---------- packed f32x2 ops on opaque u64 register pairs ----------
__device__ __forceinline__ u64 ffma2(u64 a, u64 b, u64 c) {
    u64 d; asm("fma.rn.f32x2 %0, %1, %2, %3;" : "=l"(d) : "l"(a), "l"(b), "l"(c)); return d;
}
__device__ __forceinline__ u64 pk(float lo, float hi) {
    u64 r; asm("mov.b64 %0, {%1,%2};" : "=l"(r) : "f"(lo), "f"(hi)); return r;
}
__device__ __forceinline__ float2 upk(u64 v) {
    float2 f; asm("mov.b64 {%0,%1}, %2;" : "=f"(f.x), "=f"(f.y) : "l"(v)); return f;
}
__device__ __forceinline__ u64 dup2(float v) { return pk(v, v); }

__device__ __forceinline__ float tanhapx(float x) {
    float y; asm("tanh.approx.f32 %0, %1;" : "=f"(y) : "f"(x)); return y;
}

#define NEG1U 0xBF800000BF800000ULL  // (-1.0f, -1.0f)

// sigmoid(x) = 0.5*tanh(0.5x) + 0.5  — 2 MUFU.TANH per packed pair
__device__ __forceinline__ u64 sigmoid2t(u64 v) {
    float2 f = upk(v);
    float ta = tanhapx(0.5f * f.x);
    float tb = tanhapx(0.5f * f.y);
    return pk(fmaf(0.5f, ta, 0.5f), fmaf(0.5f, tb, 0.5f));
}
__device__ __forceinline__ u64 tanh2t(u64 v) {
    float2 f = upk(v);
    return pk(tanhapx(f.x), tanhapx(f.y));
}

struct Smem {
    float4     xs[RPB][8];        // staged x chunk (32 rows x 32 cols), XOR swizzle (4KB)
    ulonglong2 wprojq[DD][4];     // [d][sub]: {Wp pair(2s,2s+1), Wg1 pair(2s,2s+1)} (16KB)
    u64        gf[RPB][TT];       // precomputed (gate, (1-gate)*decay) per row per t (7KB)
};

__global__ void __launch_bounds__(BLK, 4)
horizon_kernel(const float* __restrict__ x, const float* __restrict__ last_step,
               const float* __restrict__ W_ih, const float* __restrict__ W_hh,
               const float* __restrict__ b_ih, const float* __restrict__ b_hh,
               const float* __restrict__ Wp, const float* __restrict__ bp,
               const float* __restrict__ Wo, const float* __restrict__ bo,
               const float* __restrict__ Wg1, const float* __restrict__ bg1,
               const float* __restrict__ Wg2, const float* __restrict__ bg2,
               const float* __restrict__ log_decay, float* __restrict__ out) {
    __shared__ Smem s;
    const int tid = threadIdx.x;
    const int sub = tid & 3;        // quarter within the row (owns 2 lanes per gate)
    const int rl  = tid >> 2;       // local row 0..31
    const int rb  = blockIdx.x * RPB;
    const int L0  = 2 * sub, L1 = L0 + 1;
    const unsigned FULL = 0xFFFFFFFFu;

    // ---------------- projection weight prep (one LDS.128 per d per thread later) ----------
    for (int i = tid; i < DD * 4; i += BLK) {
        int d = i >> 2, ss = i & 3;
        s.wprojq[d][ss] = make_ulonglong2(
            pk(Wp[(2 * ss) * DD + d], Wp[(2 * ss + 1) * DD + d]),
            pk(Wg1[(2 * ss) * DD + d], Wg1[(2 * ss + 1) * DD + d]));
    }

    // ---------------- projections: thread owns h lanes (L0,L1) and g1 lanes (L0,L1) ------
    u64 accp = pk(bp[L0], bp[L1]);
    u64 accg = pk(bg1[L0], bg1[L1]);

#pragma unroll 1
    for (int c = 0; c < 8; c++) {
        __syncthreads();
#pragma unroll
        for (int k = 0; k < 2; k++) {
            int idx = k * BLK + tid;          // 0..255 float4s (32 rows x 8)
            int r = idx >> 3, q = idx & 7;
            float4 v = ((const float4*)(x + (size_t)(rb + r) * DD + c * 32))[q];
            s.xs[r][q ^ (r & 7)] = v;
        }
        __syncthreads();
#pragma unroll
        for (int q = 0; q < 8; q++) {
            float4 xv = s.xs[rl][q ^ (rl & 7)];
            int dbase = (c << 5) + (q << 2);
#pragma unroll
            for (int e = 0; e < 4; e++) {
                float xs_e = (e == 0) ? xv.x : (e == 1) ? xv.y : (e == 2) ? xv.z : xv.w;
                u64 xd = dup2(xs_e);
                ulonglong2 w = s.wprojq[dbase + e][sub];
                accp = ffma2(w.x, xd, accp);
                accg = ffma2(w.y, xd, accg);
            }
        }
    }

    u64 hq = accp;                     // h lanes (L0, L1)
    u64 g1q;
    {
        float2 f = upk(accg);
        g1q = pk(fmaxf(f.x, 0.0f), fmaxf(f.y, 0.0f));
    }

    const float last = last_step[rb + rl];

    // ---------------- precompute gate & decay combination per t (loop-invariant) ---------
    {
        u64 gA = __shfl_xor_sync(FULL, g1q, 1);
        u64 gB = __shfl_xor_sync(FULL, g1q, 2);
        u64 gC = __shfl_xor_sync(FULL, g1q, 3);
        float2 g0 = upk(g1q), g1v = upk(gA), g2v = upk(gB), g3v = upk(gC);
        float edc = __expf(log_decay[0]);
        int j0 = 2 * (sub ^ 0), j1 = 2 * (sub ^ 1), j2 = 2 * (sub ^ 2), j3 = 2 * (sub ^ 3);
#pragma unroll
        for (int k = 0; k < 7; k++) {
            int t = 4 * k + sub;
            const float* wr = Wg2 + t * HH;
            float lg = bg2[t];
            lg = fmaf(g0.x, wr[j0], lg);     lg = fmaf(g0.y, wr[j0 + 1], lg);
            lg = fmaf(g1v.x, wr[j1], lg);    lg = fmaf(g1v.y, wr[j1 + 1], lg);
            lg = fmaf(g2v.x, wr[j2], lg);    lg = fmaf(g2v.y, wr[j2 + 1], lg);
            lg = fmaf(g3v.x, wr[j3], lg);    lg = fmaf(g3v.y, wr[j3 + 1], lg);
            float gate = fmaf(0.5f, tanhapx(0.5f * lg), 0.5f);
            float gd = last * __expf(-edc * (float)(t + 1));
            s.gf[rl][t] = pk(gate, (1.0f - gate) * gd);
        }
    }

    // ---------------- hoist GRU weights into registers (slot-permuted to match shuffles) --
    u64 whr[8], whz[8], whn[8], wo4[4];
#pragma unroll
    for (int p = 0; p < 4; p++) {
        int j0 = 2 * (sub ^ p);
#pragma unroll
        for (int b = 0; b < 2; b++) {
            int j = j0 + b, idx = 2 * p + b;
            whr[idx] = pk(W_hh[L0 * HH + j],        W_hh[L1 * HH + j]);
            whz[idx] = pk(W_hh[(8 + L0) * HH + j],  W_hh[(8 + L1) * HH + j]);
            whn[idx] = pk(W_hh[(16 + L0) * HH + j], W_hh[(16 + L1) * HH + j]);
        }
        wo4[p] = pk(Wo[j0], Wo[j0 + 1]);
    }
    u64 wihr = pk(W_ih[L0], W_ih[L1]);
    u64 wihz = pk(W_ih[8 + L0], W_ih[8 + L1]);
    u64 wihn = pk(W_ih[16 + L0], W_ih[16 + L1]);
    u64 bsr  = pk(b_ih[L0] + b_hh[L0], b_ih[L1] + b_hh[L1]);
    u64 bsz  = pk(b_ih[8 + L0] + b_hh[8 + L0], b_ih[8 + L1] + b_hh[8 + L1]);
    u64 bain = pk(b_ih[16 + L0], b_ih[16 + L1]);
    u64 bahn = pk(b_hh[16 + L0], b_hh[16 + L1]);
    const float bo_r = bo[0];

    // ---------------- GRU rollout: 4 threads/row, weights in registers ----------------
    float cur = last;
    float* outrow = out + (size_t)(rb + rl) * TT;

#pragma unroll 1
    for (int t = 0; t <= TT; t++) {
        // butterfly h-exchange: slot p holds lanes (2*(sub^p), +1)
        u64 h1 = __shfl_xor_sync(FULL, hq, 1);
        u64 h2 = __shfl_xor_sync(FULL, hq, 2);
        u64 h3 = __shfl_xor_sync(FULL, hq, 3);
        // pred(t-1) = Wo . h + bo  (computed locally by every thread, no reduction)
        u64 pp = ffma2(hq, wo4[0], 0ULL);
        pp = ffma2(h1, wo4[1], pp);
        pp = ffma2(h2, wo4[2], pp);
        pp = ffma2(h3, wo4[3], pp);
        float2 pf = upk(pp);
        float p = pf.x + pf.y + bo_r;
        if (t > 0) {
            cur = p;
            if (((t - 1) & 3) == sub) {
                float2 gg = upk(s.gf[rl][t - 1]);
                outrow[t - 1] = fmaf(gg.x, p, gg.y);   // gate*pred + (1-gate)*decay
            }
        }
        if (t == TT) break;

        float2 f0 = upk(hq), f1 = upk(h1), f2 = upk(h2), f3 = upk(h3);
        u64 curd = dup2(cur);
        u64 ar = ffma2(wihr, curd, bsr);
        u64 az = ffma2(wihz, curd, bsz);
        u64 ai = ffma2(wihn, curd, bain);
        u64 ah = bahn;
#define STEPJ(idx, hval) { u64 hd = dup2(hval); \
        ar = ffma2(whr[idx], hd, ar); \
        az = ffma2(whz[idx], hd, az); \
        ah = ffma2(whn[idx], hd, ah); }
        STEPJ(0, f0.x) STEPJ(1, f0.y)
        STEPJ(2, f1.x) STEPJ(3, f1.y)
        STEPJ(4, f2.x) STEPJ(5, f2.y)
        STEPJ(6, f3.x) STEPJ(7, f3.y)
#undef STEPJ
        u64 r = sigmoid2t(ar);
        u64 z = sigmoid2t(az);
        u64 n = tanh2t(ffma2(r, ah, ai));
        u64 d = ffma2(n, NEG1U, hq);     // h - n
        hq = ffma2(z, d, n);             // n + z*(h-n)
    }
}

extern "C" void kernel_launch(void* const* d_in, const int* in_sizes, int n_in,
                              void* d_out, int out_size) {
    const float* x         = (const float*)d_in[0];
    const float* last_step = (const float*)d_in[1];
    const float* W_ih      = (const float*)d_in[2];
    const float* W_hh      = (const float*)d_in[3];
    const float* b_ih      = (const float*)d_in[4];
    const float* b_hh      = (const float*)d_in[5];
    const float* Wp        = (const float*)d_in[6];
    const float* bp        = (const float*)d_in[7];
    const float* Wo        = (const float*)d_in[8];
    const float* bo        = (const float*)d_in[9];
    const float* Wg1       = (const float*)d_in[10];
    const float* bg1       = (const float*)d_in[11];
    const float* Wg2       = (const float*)d_in[12];
    const float* bg2       = (const float*)d_in[13];
    const float* log_decay = (const float*)d_in[14];
    float* out = (float*)d_out;

    horizon_kernel<<<ROWS / RPB, BLK>>>(x, last_step, W_ih, W_hh, b_ih, b_hh,
                                        Wp, bp, Wo, bo, Wg1, bg1, Wg2, bg2,
                                        log_decay, out);
}